// round 14
// baseline (speedup 1.0000x reference)
#include <cuda_runtime.h>
#include <cuda_fp16.h>
#include <cstdint>
#include <math.h>

#define LL 256
#define BB 256
#define BHALF 128
#define HH 256
#define CC 16
#define YY 32
#define NSTEPS 255
#define NCTA 256
#define NTHR 256
#define LOSCALE 2048.0f
#define INVLOSCALE 4.8828125e-4f

// ---- dynamic smem byte offsets (per CTA ~100 KB -> 2 CTAs/SM) ----
#define SM_W2HI 0          // 16 KB  W2t hi fp16, blocked SW128 [32n][256k]
#define SM_W2LO 16384      // 16 KB  W2t lo (x2048)
#define SM_W1   32768      // 2 KB   ull[256]
#define SM_B1   34816      // 8 B
#define SM_PSUM 35072      // 2 KB   (256 ull)
#define SM_XBUF 37120      // 64 KB: stage1 2x32KB fp32 halves / stage2 2x32KB fp16 A
#define SMEM_BYTES 102656  // 37120 + 65536

// ---------------- global scratch ----------------
__device__ float g_zT[HH * BB];                 // z transposed [h][b] fp32
__device__ __half g_hidhi[BB * HH];             // hid [b][h] fp16 hi
__device__ __half g_hidlo[BB * HH];             // hid [b][h] fp16 lo (x2048)
__device__ float g_dstep[NSTEPS * BB * CC];
__device__ float g_zseq[LL * HH * BB];
__device__ unsigned g_bar_count;

// ---------------- fast tanh (final kernel only; no recurrence there) ---------
__device__ __forceinline__ float tanh_fast(float x) {
    float e = __expf(2.0f * x);
    return 1.0f - __fdividef(2.0f, e + 1.0f);
}

// ---------------- packed f32x2 helpers ----------------
#define FMA2(acc, a, b) asm("fma.rn.f32x2 %0, %1, %2, %0;" : "+l"(acc) : "l"(a), "l"(b))
#define PACK2(r, lo, hi) asm("mov.b64 %0, {%1, %2};" : "=l"(r) : "f"(lo), "f"(hi))
#define UNPACK2(lo, hi, r) asm("mov.b64 {%0, %1}, %2;" : "=f"(lo), "=f"(hi) : "l"(r))

// ---------------- cp.async ----------------
__device__ __forceinline__ void cpasync16(unsigned saddr, const void* g) {
    asm volatile("cp.async.cg.shared.global [%0], [%1], 16;" :: "r"(saddr), "l"(g));
}
#define CP_COMMIT() asm volatile("cp.async.commit_group;")
#define CP_WAIT(n)  asm volatile("cp.async.wait_group %0;" :: "n"(n))

// stage1: one 64h x 128b fp32 chunk (32 KB) of this CTA's batch half
__device__ __forceinline__ void load_zhalf(unsigned sdst, const float* zsrc, int g, int t) {
    #pragma unroll
    for (int i = 0; i < 8; i++) {
        int u = t * 8 + i;              // 0..2047
        int kk = u >> 5, sg = u & 31;   // row, 16B segment
        cpasync16(sdst + (unsigned)(kk * 512 + sg * 16),
                  zsrc + (size_t)kk * BB + g * BHALF + sg * 4);
    }
    CP_COMMIT();
}

// stage2: one 128b x 64k fp16 A chunk (hi 16KB + lo 16KB), SW128-swizzled rows
__device__ __forceinline__ void loadA2h(unsigned base, int g, int kc, int t) {
    #pragma unroll
    for (int i = 0; i < 4; i++) {
        int u = t * 4 + i;              // 0..1023
        int row = u >> 3, seg = u & 7;  // local batch row 0..127
        unsigned sw = (unsigned)(row * 128 + ((seg ^ (row & 7)) << 4));
        cpasync16(base + sw,
                  g_hidhi + (size_t)(g * BHALF + row) * HH + kc * 64 + seg * 8);
    }
    #pragma unroll
    for (int i = 0; i < 4; i++) {
        int u = t * 4 + i;
        int row = u >> 3, seg = u & 7;
        unsigned sw = (unsigned)(row * 128 + ((seg ^ (row & 7)) << 4));
        cpasync16(base + 16384u + sw,
                  g_hidlo + (size_t)(g * BHALF + row) * HH + kc * 64 + seg * 8);
    }
    CP_COMMIT();
}

// ---------------- ldmatrix / mma ----------------
__device__ __forceinline__ void ldmA(uint32_t* r, unsigned abase, int b0, int kt, int lane) {
    int q = lane >> 3;
    int row = b0 + (lane & 7) + ((q & 1) << 3);
    int seg = 2 * kt + (q >> 1);
    unsigned addr = abase + (unsigned)(row * 128 + ((seg ^ (row & 7)) << 4));
    asm volatile("ldmatrix.sync.aligned.m8n8.x4.shared.b16 {%0,%1,%2,%3}, [%4];"
        : "=r"(r[0]), "=r"(r[1]), "=r"(r[2]), "=r"(r[3]) : "r"(addr));
}

// W2t blocked: byte(n,k) = ((n>>3)+(k>>6)*4)*1024 + (n&7)*128 + (k&63)*2, XOR-swizzled
__device__ __forceinline__ void ldmB(uint32_t* r, unsigned mbase, int n0, int ktg, int lane) {
    int sel = lane >> 3;
    int n = n0 + ((sel >> 1) << 3) + (lane & 7);
    int k = ktg * 16 + ((sel & 1) << 3);
    unsigned byte = (unsigned)((((n >> 3) + (k >> 6) * 4) << 10) + ((n & 7) << 7) + ((k & 63) << 1));
    unsigned sw = byte ^ ((byte >> 3) & 0x70u);
    asm volatile("ldmatrix.sync.aligned.m8n8.x4.shared.b16 {%0,%1,%2,%3}, [%4];"
        : "=r"(r[0]), "=r"(r[1]), "=r"(r[2]), "=r"(r[3]) : "r"(mbase + sw));
}

__device__ __forceinline__ void mmaf16(float* c, const uint32_t* a, const uint32_t* b) {
    asm volatile("mma.sync.aligned.m16n8k16.row.col.f32.f16.f16.f32 "
        "{%0,%1,%2,%3}, {%4,%5,%6,%7}, {%8,%9}, {%0,%1,%2,%3};"
        : "+f"(c[0]), "+f"(c[1]), "+f"(c[2]), "+f"(c[3])
        : "r"(a[0]), "r"(a[1]), "r"(a[2]), "r"(a[3]), "r"(b[0]), "r"(b[1]));
}

// ---------------- grid barrier (single counter; release fence only) ----------
__device__ __forceinline__ void gridbar(unsigned target) {
    __threadfence();
    __syncthreads();
    if (threadIdx.x == 0) {
        atomicAdd(&g_bar_count, 1u);
        volatile unsigned* p = &g_bar_count;
        while (*p < target) { __nanosleep(20); }
    }
    __syncthreads();
}

// ---------------- prep ----------------
__device__ __forceinline__ float Xv(const float* ts, const float* us, int l, int b, int c) {
    return (c == 0) ? ts[(size_t)l * BB + b]
                    : us[((size_t)l * BB + b) * (CC - 1) + (c - 1)];
}

__global__ void prep_kernel(const float* __restrict__ ts, const float* __restrict__ us) {
    int k = blockIdx.x;
    int b = threadIdx.x;
    if (k == 0 && b == 0) g_bar_count = 0u;

    float s  = ts[(size_t)k * BB];
    float dt = ts[(size_t)(k + 1) * BB] - s;
    int idx = (int)floorf(s);
    idx = idx < 0 ? 0 : (idx > LL - 2 ? LL - 2 : idx);
    float tau = s - (float)idx;
    float h00p = 6.f * tau * tau - 6.f * tau;
    float h10p = 3.f * tau * tau - 4.f * tau + 1.f;
    float h11p = 3.f * tau * tau - 2.f * tau;

    float* dst = g_dstep + ((size_t)k * BB + b) * CC;
    #pragma unroll
    for (int c = 0; c < CC; c++) {
        float x_i  = Xv(ts, us, idx, b, c);
        float x_ip = Xv(ts, us, idx + 1, b, c);
        float di   = (idx == 0) ? (x_ip - x_i) : (x_i - Xv(ts, us, idx - 1, b, c));
        float dip  = x_ip - x_i;
        float val  = h00p * (x_i - x_ip) + h10p * di + h11p * dip;
        dst[c] = dt * val;
    }
}

// ---------------- persistent scan kernel: 256 CTAs (2/SM), batch-split -------
// CTA j: g = j>>7 selects batch half [128g, 128g+128); jp = j&127 selects
// W1 cols {2jp, 2jp+1} and W2 cols [32jp, 32jp+32).
__global__ void __launch_bounds__(NTHR, 2)
scan_kernel(const float* __restrict__ W1, const float* __restrict__ b1,
            const float* __restrict__ W2, const float* __restrict__ b2,
            const float* __restrict__ h0) {
    extern __shared__ char smc[];
    const unsigned sbase = (unsigned)__cvta_generic_to_shared(smc);
    float* b1s = (float*)(smc + SM_B1);
    unsigned long long* w1s  = (unsigned long long*)(smc + SM_W1);
    unsigned long long* psum = (unsigned long long*)(smc + SM_PSUM);

    const int t    = threadIdx.x;       // 0..255
    const int b    = t & 127;           // local batch
    const int half = t >> 7;            // stage1 column half
    const int wid  = t >> 5;            // 0..7
    const int lane = t & 31;
    const int j    = blockIdx.x;        // 0..255
    const int jp   = j & 127;
    const int g    = j >> 7;

    // --- one-time: W2 slice -> fp16 hi/lo(x2048), transposed [n][k], blocked SW128
    for (int idx = t; idx < 32 * 256; idx += NTHR) {
        int n = idx >> 8, k = idx & 255;
        float w = W2[(size_t)k * (HH * CC) + 32 * jp + n];
        __half whi = __float2half_rn(w);
        float rem = w - __half2float(whi);
        unsigned byte = (unsigned)((((n >> 3) + (k >> 6) * 4) << 10) + ((n & 7) << 7) + ((k & 63) << 1));
        unsigned sw = byte ^ ((byte >> 3) & 0x70u);
        *(__half*)(smc + SM_W2HI + sw) = whi;
        *(__half*)(smc + SM_W2LO + sw) = __float2half_rn(rem * LOSCALE);
    }
    {
        float2 w1v = *(const float2*)(W1 + (size_t)t * HH + 2 * jp);
        unsigned long long w1p; PACK2(w1p, w1v.x, w1v.y);
        w1s[t] = w1p;
        if (t < 2) b1s[t] = b1[2 * jp + t];
    }

    // readout ownership: warp w -> local batches [16w,16w+16); quads own rb0, rb0+8
    const int b0w = 16 * wid;
    const int rb0 = b0w + (lane >> 2);
    const int rb1 = rb0 + 8;
    const int bg0 = g * BHALF + rb0;    // global batch rows
    const int bg1 = g * BHALF + rb1;
    const int c0l = 2 * (lane & 3);

    float b2v[8];
    #pragma unroll
    for (int nt = 0; nt < 4; nt++) {
        b2v[nt * 2]     = b2[32 * jp + nt * 8 + c0l];
        b2v[nt * 2 + 1] = b2[32 * jp + nt * 8 + c0l + 1];
    }

    float zc00 = h0[(size_t)bg0 * HH + 2 * jp];
    float zc01 = h0[(size_t)bg0 * HH + 2 * jp + 1];
    float zc10 = h0[(size_t)bg1 * HH + 2 * jp];
    float zc11 = h0[(size_t)bg1 * HH + 2 * jp + 1];
    if ((lane & 3) == 0) {
        g_zT[(2 * jp) * BB + bg0]     = zc00;
        g_zT[(2 * jp + 1) * BB + bg0] = zc01;
        g_zT[(2 * jp) * BB + bg1]     = zc10;
        g_zT[(2 * jp + 1) * BB + bg1] = zc11;
        g_zseq[(size_t)(2 * jp) * BB + bg0]     = zc00;
        g_zseq[(size_t)(2 * jp + 1) * BB + bg0] = zc01;
        g_zseq[(size_t)(2 * jp) * BB + bg1]     = zc10;
        g_zseq[(size_t)(2 * jp + 1) * BB + bg1] = zc11;
    }

    unsigned ep = 0;
    gridbar((++ep) * NCTA);   // weights + z v0 visible everywhere

    #pragma unroll 1
    for (int s = 0; s < NSTEPS; ++s) {
        // ===== stage 1: hid[bhalf, 2jp+half] = relu(z @ W1pair + b1) ============
        // 4 chunks of 64 h-rows x 128 b (32 KB each), double-buffered.
        {
            unsigned long long acc01;
            if (half == 0) { PACK2(acc01, b1s[0], b1s[1]); }
            else           { PACK2(acc01, 0.f, 0.f); }

            load_zhalf(sbase + SM_XBUF, g_zT, g, t);
            load_zhalf(sbase + SM_XBUF + 32768u, g_zT + 64 * BB, g, t);
            CP_WAIT(1);
            __syncthreads();
            #pragma unroll 1
            for (int c = 0; c < 4; ++c) {
                const float* buf = (const float*)(smc + SM_XBUF + (c & 1) * 32768);
                if ((c & 1) == half) {
                    #pragma unroll 8
                    for (int kk = 0; kk < 64; kk++) {
                        float zv = buf[kk * BHALF + b];
                        unsigned long long aa; PACK2(aa, zv, zv);
                        FMA2(acc01, aa, w1s[c * 64 + kk]);
                    }
                }
                __syncthreads();           // all threads done reading buf (c&1)
                if (c + 2 < 4) {
                    load_zhalf(sbase + SM_XBUF + (unsigned)((c & 1) * 32768),
                               g_zT + (size_t)(c + 2) * 64 * BB, g, t);
                    CP_WAIT(1);
                    __syncthreads();
                } else if (c + 1 < 4) {
                    CP_WAIT(0);
                    __syncthreads();
                }
            }
            psum[t] = acc01;
            __syncthreads();
            unsigned long long other = psum[t ^ 128];
            float slo, shi, olo, ohi;
            UNPACK2(slo, shi, acc01);
            UNPACK2(olo, ohi, other);
            float a0 = fmaxf(slo + olo, 0.f);
            float a1 = fmaxf(shi + ohi, 0.f);
            float a = (half == 0) ? a0 : a1;
            __half hv = __float2half_rn(a);
            float rem = a - __half2float(hv);
            g_hidhi[(size_t)(g * BHALF + b) * HH + 2 * jp + half] = hv;
            g_hidlo[(size_t)(g * BHALF + b) * HH + 2 * jp + half] =
                __float2half_rn(rem * LOSCALE);
        }
        gridbar((++ep) * NCTA);

        // ---- prefetch this step's d vectors (independent of hid) ----
        float2 dA0, dB0, dA1, dB1;
        {
            const float* dp0 = g_dstep + ((size_t)s * BB + bg0) * CC;
            const float* dp1 = g_dstep + ((size_t)s * BB + bg1) * CC;
            dA0 = *(const float2*)(dp0 + c0l);
            dB0 = *(const float2*)(dp0 + c0l + 8);
            dA1 = *(const float2*)(dp1 + c0l);
            dB1 = *(const float2*)(dp1 + c0l + 8);
        }

        // ===== stage 2: G[128b, 32n] = hid_half @ W2slice via MMA fp16-split ====
        float cfrH[4][4], cfrL[4][4];
        #pragma unroll
        for (int nt = 0; nt < 4; nt++)
            #pragma unroll
            for (int q = 0; q < 4; q++) { cfrH[nt][q] = 0.f; cfrL[nt][q] = 0.f; }

        {
            loadA2h(sbase + SM_XBUF, g, 0, t);
            CP_WAIT(0);
            __syncthreads();
            #pragma unroll 1
            for (int kc = 0; kc < 4; ++kc) {
                if (kc < 3)
                    loadA2h(sbase + SM_XBUF + (unsigned)(((kc + 1) & 1) * 32768),
                            g, kc + 1, t);
                unsigned ab = sbase + SM_XBUF + (unsigned)((kc & 1) * 32768);
                #pragma unroll
                for (int kt = 0; kt < 4; ++kt) {
                    uint32_t ahi[4], alo[4], bh[8], bl[8];
                    ldmA(ahi, ab, b0w, kt, lane);
                    ldmA(alo, ab + 16384u, b0w, kt, lane);
                    int ktg = kc * 4 + kt;
                    ldmB(bh,     sbase + SM_W2HI, 0,  ktg, lane);
                    ldmB(bh + 4, sbase + SM_W2HI, 16, ktg, lane);
                    ldmB(bl,     sbase + SM_W2LO, 0,  ktg, lane);
                    ldmB(bl + 4, sbase + SM_W2LO, 16, ktg, lane);
                    #pragma unroll
                    for (int nt = 0; nt < 4; nt++) {
                        mmaf16(cfrH[nt], ahi, bh + 2 * nt);
                        mmaf16(cfrL[nt], ahi, bl + 2 * nt);
                        mmaf16(cfrL[nt], alo, bh + 2 * nt);
                    }
                }
                if (kc < 3) { CP_WAIT(0); __syncthreads(); }
            }
        }

        // ===== readout: tanh + d contraction, quad reduction =====
        {
            float gg[4][4];
            #pragma unroll
            for (int nt = 0; nt < 4; nt++)
                #pragma unroll
                for (int q = 0; q < 4; q++)
                    gg[nt][q] = fmaf(cfrL[nt][q], INVLOSCALE, cfrH[nt][q]);

            float s00 = tanhf(gg[0][0] + b2v[0]) * dA0.x + tanhf(gg[0][1] + b2v[1]) * dA0.y
                      + tanhf(gg[1][0] + b2v[2]) * dB0.x + tanhf(gg[1][1] + b2v[3]) * dB0.y;
            float s01 = tanhf(gg[2][0] + b2v[4]) * dA0.x + tanhf(gg[2][1] + b2v[5]) * dA0.y
                      + tanhf(gg[3][0] + b2v[6]) * dB0.x + tanhf(gg[3][1] + b2v[7]) * dB0.y;
            float s10 = tanhf(gg[0][2] + b2v[0]) * dA1.x + tanhf(gg[0][3] + b2v[1]) * dA1.y
                      + tanhf(gg[1][2] + b2v[2]) * dB1.x + tanhf(gg[1][3] + b2v[3]) * dB1.y;
            float s11 = tanhf(gg[2][2] + b2v[4]) * dA1.x + tanhf(gg[2][3] + b2v[5]) * dA1.y
                      + tanhf(gg[3][2] + b2v[6]) * dB1.x + tanhf(gg[3][3] + b2v[7]) * dB1.y;

            s00 += __shfl_xor_sync(0xFFFFFFFF, s00, 1); s00 += __shfl_xor_sync(0xFFFFFFFF, s00, 2);
            s01 += __shfl_xor_sync(0xFFFFFFFF, s01, 1); s01 += __shfl_xor_sync(0xFFFFFFFF, s01, 2);
            s10 += __shfl_xor_sync(0xFFFFFFFF, s10, 1); s10 += __shfl_xor_sync(0xFFFFFFFF, s10, 2);
            s11 += __shfl_xor_sync(0xFFFFFFFF, s11, 1); s11 += __shfl_xor_sync(0xFFFFFFFF, s11, 2);

            zc00 += s00; zc01 += s01; zc10 += s10; zc11 += s11;
            if ((lane & 3) == 0) {
                g_zT[(2 * jp) * BB + bg0]     = zc00;
                g_zT[(2 * jp + 1) * BB + bg0] = zc01;
                g_zT[(2 * jp) * BB + bg1]     = zc10;
                g_zT[(2 * jp + 1) * BB + bg1] = zc11;
                size_t zs = (size_t)(s + 1) * (HH * BB);
                g_zseq[zs + (2 * jp) * BB + bg0]     = zc00;
                g_zseq[zs + (2 * jp + 1) * BB + bg0] = zc01;
                g_zseq[zs + (2 * jp) * BB + bg1]     = zc10;
                g_zseq[zs + (2 * jp + 1) * BB + bg1] = zc11;
            }
        }
        gridbar((++ep) * NCTA);
    }
}

// ---------------- final projection ----------------
#define JCH 32
__global__ void __launch_bounds__(256, 2)
final_kernel(const float* __restrict__ dW1, const float* __restrict__ db1,
             const float* __restrict__ dW2, const float* __restrict__ db2,
             float* __restrict__ out) {
    const int l = blockIdx.x, t = threadIdx.x;
    __shared__ float w1s[256 * JCH];
    __shared__ float w2s[JCH * 32];
    __shared__ float db1s[JCH];

    unsigned long long oacc[16];
    #pragma unroll
    for (int q = 0; q < 16; q++) PACK2(oacc[q], db2[2 * q], db2[2 * q + 1]);

    for (int ch = 0; ch < 512 / JCH; ++ch) {
        const int j0 = ch * JCH;
        {
            const float4* src = (const float4*)(dW1 + (size_t)t * 512 + j0);
            float4* dst = (float4*)(w1s + t * JCH);
            #pragma unroll
            for (int q = 0; q < JCH / 4; q++) dst[q] = src[q];
            for (int q = t; q < JCH * 32; q += 256) w2s[q] = dW2[(size_t)j0 * 32 + q];
            if (t < JCH) db1s[t] = db1[j0 + t];
        }
        __syncthreads();

        unsigned long long hacc[JCH / 2];
        #pragma unroll
        for (int p = 0; p < JCH / 2; p++) PACK2(hacc[p], db1s[2 * p], db1s[2 * p + 1]);
        {
            const float* zp = g_zseq + (size_t)l * (HH * BB) + t;
            #pragma unroll 4
            for (int k = 0; k < HH; k++) {
                float zv = zp[(size_t)k * BB];
                unsigned long long aa; PACK2(aa, zv, zv);
                const ulonglong2* wp = (const ulonglong2*)(w1s + k * JCH);
                #pragma unroll
                for (int q = 0; q < JCH / 4; q++) {
                    ulonglong2 w = wp[q];
                    FMA2(hacc[2 * q],     aa, w.x);
                    FMA2(hacc[2 * q + 1], aa, w.y);
                }
            }
        }
        #pragma unroll
        for (int p = 0; p < JCH / 2; p++) {
            float lo, hi; UNPACK2(lo, hi, hacc[p]);
            float t0 = tanh_fast(lo), t1 = tanh_fast(hi);
            unsigned long long aa0, aa1; PACK2(aa0, t0, t0); PACK2(aa1, t1, t1);
            const unsigned long long* r0 = (const unsigned long long*)(w2s + (2 * p) * 32);
            const unsigned long long* r1 = (const unsigned long long*)(w2s + (2 * p + 1) * 32);
            #pragma unroll
            for (int q = 0; q < 16; q++) FMA2(oacc[q], aa0, r0[q]);
            #pragma unroll
            for (int q = 0; q < 16; q++) FMA2(oacc[q], aa1, r1[q]);
        }
        __syncthreads();
    }

    float* op = out + ((size_t)l * BB + t) * YY;
    #pragma unroll
    for (int q = 0; q < 16; q++) {
        float lo, hi; UNPACK2(lo, hi, oacc[q]);
        op[2 * q] = lo; op[2 * q + 1] = hi;
    }
}

// ---------------- launch ----------------
extern "C" void kernel_launch(void* const* d_in, const int* in_sizes, int n_in,
                              void* d_out, int out_size) {
    const float* ts  = (const float*)d_in[0];
    const float* us  = (const float*)d_in[1];
    const float* h0  = (const float*)d_in[2];
    const float* W1  = (const float*)d_in[3];
    const float* b1  = (const float*)d_in[4];
    const float* W2  = (const float*)d_in[5];
    const float* b2  = (const float*)d_in[6];
    const float* dW1 = (const float*)d_in[7];
    const float* db1 = (const float*)d_in[8];
    const float* dW2 = (const float*)d_in[9];
    const float* db2 = (const float*)d_in[10];

    cudaFuncSetAttribute(scan_kernel,
                         cudaFuncAttributeMaxDynamicSharedMemorySize, SMEM_BYTES);

    prep_kernel<<<NSTEPS, 256>>>(ts, us);
    scan_kernel<<<NCTA, NTHR, SMEM_BYTES>>>(W1, b1, W2, b2, h0);
    final_kernel<<<LL, 256>>>(dW1, db1, dW2, db2, (float*)d_out);
}

// round 15
// speedup vs baseline: 1.3525x; 1.3525x over previous
#include <cuda_runtime.h>
#include <cuda_fp16.h>
#include <cstdint>
#include <math.h>

#define LL 256
#define BB 256
#define HH 256
#define CC 16
#define YY 32
#define NSTEPS 255
#define NCTA 128
#define NTHR 512
#define LOSCALE 2048.0f
#define INVLOSCALE 4.8828125e-4f

// ---- dynamic smem byte offsets (verified: 40960 + 131072 = 172032) ----
#define SM_W2HI 0          // 16 KB  W2t hi fp16, blocked SW128
#define SM_W2LO 16384      // 16 KB  W2t lo (x2048)
#define SM_W1   32768      // 2 KB   ull[256]
#define SM_B1   34816      // 8 B
#define SM_PSUM 35072      // 4 KB
#define SM_XBUF 40960      // 128 KB: stage1 2x64KB fp32 / stage2 2x64KB fp16 A bufs
#define SMEM_BYTES 172032

// ---------------- global scratch ----------------
__device__ float g_zT[HH * BB];                 // z transposed [h][b] fp32
__device__ __half g_hidhi[BB * HH];             // hid [b][h] fp16 hi
__device__ __half g_hidlo[BB * HH];             // hid [b][h] fp16 lo (x2048)
__device__ float g_dstep[NSTEPS * BB * CC];
__device__ float g_zseq[LL * HH * BB];
__device__ unsigned g_arr[NCTA];                // per-CTA arrival slots (no convoy)

// ---------------- fast tanh (final kernel only; no recurrence amplification) -
__device__ __forceinline__ float tanh_fast(float x) {
    float e = __expf(2.0f * x);
    return 1.0f - __fdividef(2.0f, e + 1.0f);
}

// ---------------- packed f32x2 helpers ----------------
#define FMA2(acc, a, b) asm("fma.rn.f32x2 %0, %1, %2, %0;" : "+l"(acc) : "l"(a), "l"(b))
#define PACK2(r, lo, hi) asm("mov.b64 %0, {%1, %2};" : "=l"(r) : "f"(lo), "f"(hi))
#define UNPACK2(lo, hi, r) asm("mov.b64 {%0, %1}, %2;" : "=f"(lo), "=f"(hi) : "l"(r))

// ---------------- cp.async ----------------
__device__ __forceinline__ void cpasync16(unsigned saddr, const void* g) {
    asm volatile("cp.async.cg.shared.global [%0], [%1], 16;" :: "r"(saddr), "l"(g));
}
#define CP_COMMIT() asm volatile("cp.async.commit_group;")
#define CP_WAIT(n)  asm volatile("cp.async.wait_group %0;" :: "n"(n))

// stage1: one 64x256 fp32 chunk (64 KB), 512 threads x 8 x 16B
__device__ __forceinline__ void load_chunk64(unsigned sdst, const float* src, int t) {
    unsigned s = sdst + (unsigned)t * 16u;
    const float* g = src + t * 4;
    #pragma unroll
    for (int i = 0; i < 8; i++)
        cpasync16(s + i * 8192u, g + i * 2048);
    CP_COMMIT();
}

// stage2: one 256b x 64k fp16 A chunk (hi 32KB + lo 32KB), SW128-swizzled rows
__device__ __forceinline__ void loadA2(unsigned base, int kc, int t) {
    #pragma unroll
    for (int i = 0; i < 4; i++) {
        int u = t * 4 + i;                  // 0..2047
        int row = u >> 3, seg = u & 7;
        unsigned sw = (unsigned)(row * 128 + ((seg ^ (row & 7)) << 4));
        cpasync16(base + sw, g_hidhi + (size_t)row * HH + kc * 64 + seg * 8);
    }
    #pragma unroll
    for (int i = 0; i < 4; i++) {
        int u = t * 4 + i;
        int row = u >> 3, seg = u & 7;
        unsigned sw = (unsigned)(row * 128 + ((seg ^ (row & 7)) << 4));
        cpasync16(base + 32768u + sw, g_hidlo + (size_t)row * HH + kc * 64 + seg * 8);
    }
    CP_COMMIT();
}

// ---------------- ldmatrix / mma ----------------
__device__ __forceinline__ void ldmA(uint32_t* r, unsigned abase, int b0, int kt, int lane) {
    int q = lane >> 3;
    int row = b0 + (lane & 7) + ((q & 1) << 3);
    int seg = 2 * kt + (q >> 1);
    unsigned addr = abase + (unsigned)(row * 128 + ((seg ^ (row & 7)) << 4));
    asm volatile("ldmatrix.sync.aligned.m8n8.x4.shared.b16 {%0,%1,%2,%3}, [%4];"
        : "=r"(r[0]), "=r"(r[1]), "=r"(r[2]), "=r"(r[3]) : "r"(addr));
}

// W2t blocked: byte(n,k) = ((n>>3)+(k>>6)*4)*1024 + (n&7)*128 + (k&63)*2, XOR-swizzled
__device__ __forceinline__ void ldmB(uint32_t* r, unsigned mbase, int n0, int ktg, int lane) {
    int sel = lane >> 3;
    int n = n0 + ((sel >> 1) << 3) + (lane & 7);
    int k = ktg * 16 + ((sel & 1) << 3);
    unsigned byte = (unsigned)((((n >> 3) + (k >> 6) * 4) << 10) + ((n & 7) << 7) + ((k & 63) << 1));
    unsigned sw = byte ^ ((byte >> 3) & 0x70u);
    asm volatile("ldmatrix.sync.aligned.m8n8.x4.shared.b16 {%0,%1,%2,%3}, [%4];"
        : "=r"(r[0]), "=r"(r[1]), "=r"(r[2]), "=r"(r[3]) : "r"(mbase + sw));
}

__device__ __forceinline__ void mmaf16(float* c, const uint32_t* a, const uint32_t* b) {
    asm volatile("mma.sync.aligned.m16n8k16.row.col.f32.f16.f16.f32 "
        "{%0,%1,%2,%3}, {%4,%5,%6,%7}, {%8,%9}, {%0,%1,%2,%3};"
        : "+f"(c[0]), "+f"(c[1]), "+f"(c[2]), "+f"(c[3])
        : "r"(a[0]), "r"(a[1]), "r"(a[2]), "r"(a[3]), "r"(b[0]), "r"(b[1]));
}

// ---------------- slot-array grid barrier (no atomic convoy) ------------------
// Arrival: one atomicExch to the CTA's OWN slot (128 distinct addrs, pipelined).
// Wait: warp 0 scans all 128 slots with one LDG.128 volatile per lane + vote.
__device__ __forceinline__ void gridbar(unsigned ep, int j, int wid, int lane) {
    __threadfence();                    // release: drain my stores to L2
    __syncthreads();
    if (threadIdx.x == 0) atomicExch(&g_arr[j], ep);
    if (wid == 0) {
        const unsigned* base = g_arr + lane * 4;
        for (;;) {
            unsigned v0, v1, v2, v3;
            asm volatile("ld.volatile.global.v4.u32 {%0,%1,%2,%3}, [%4];"
                : "=r"(v0), "=r"(v1), "=r"(v2), "=r"(v3) : "l"(base));
            bool ok = (v0 >= ep) & (v1 >= ep) & (v2 >= ep) & (v3 >= ep);
            if (__all_sync(0xFFFFFFFFu, ok)) break;
            __nanosleep(20);
        }
    }
    __syncthreads();
}

// ---------------- prep ----------------
__device__ __forceinline__ float Xv(const float* ts, const float* us, int l, int b, int c) {
    return (c == 0) ? ts[(size_t)l * BB + b]
                    : us[((size_t)l * BB + b) * (CC - 1) + (c - 1)];
}

__global__ void prep_kernel(const float* __restrict__ ts, const float* __restrict__ us) {
    int k = blockIdx.x;
    int b = threadIdx.x;
    if (k == 0 && b < NCTA) g_arr[b] = 0u;   // reset slots each launch/replay

    float s  = ts[(size_t)k * BB];
    float dt = ts[(size_t)(k + 1) * BB] - s;
    int idx = (int)floorf(s);
    idx = idx < 0 ? 0 : (idx > LL - 2 ? LL - 2 : idx);
    float tau = s - (float)idx;
    float h00p = 6.f * tau * tau - 6.f * tau;
    float h10p = 3.f * tau * tau - 4.f * tau + 1.f;
    float h11p = 3.f * tau * tau - 2.f * tau;

    float* dst = g_dstep + ((size_t)k * BB + b) * CC;
    #pragma unroll
    for (int c = 0; c < CC; c++) {
        float x_i  = Xv(ts, us, idx, b, c);
        float x_ip = Xv(ts, us, idx + 1, b, c);
        float di   = (idx == 0) ? (x_ip - x_i) : (x_i - Xv(ts, us, idx - 1, b, c));
        float dip  = x_ip - x_i;
        float val  = h00p * (x_i - x_ip) + h10p * di + h11p * dip;
        dst[c] = dt * val;
    }
}

// ---------------- persistent scan kernel (R12 structure) ----------------------
__global__ void __launch_bounds__(NTHR, 1)
scan_kernel(const float* __restrict__ W1, const float* __restrict__ b1,
            const float* __restrict__ W2, const float* __restrict__ b2,
            const float* __restrict__ h0) {
    extern __shared__ char smc[];
    const unsigned sbase = (unsigned)__cvta_generic_to_shared(smc);
    float* b1s = (float*)(smc + SM_B1);
    unsigned long long* w1s  = (unsigned long long*)(smc + SM_W1);
    unsigned long long* psum = (unsigned long long*)(smc + SM_PSUM);

    const int t    = threadIdx.x;
    const int b    = t & 255;
    const int half = t >> 8;
    const int wid  = t >> 5;
    const int lane = t & 31;
    const int j    = blockIdx.x;

    // --- one-time: W2 slice -> fp16 hi/lo(x2048), transposed [n][k], blocked SW128
    for (int idx = t; idx < 32 * 256; idx += NTHR) {
        int n = idx >> 8, k = idx & 255;
        float w = W2[(size_t)k * (HH * CC) + 32 * j + n];
        __half whi = __float2half_rn(w);
        float rem = w - __half2float(whi);
        unsigned byte = (unsigned)((((n >> 3) + (k >> 6) * 4) << 10) + ((n & 7) << 7) + ((k & 63) << 1));
        unsigned sw = byte ^ ((byte >> 3) & 0x70u);
        *(__half*)(smc + SM_W2HI + sw) = whi;
        *(__half*)(smc + SM_W2LO + sw) = __float2half_rn(rem * LOSCALE);
    }
    if (t < 256) {
        float2 w1v = *(const float2*)(W1 + (size_t)t * HH + 2 * j);
        unsigned long long w1p; PACK2(w1p, w1v.x, w1v.y);
        w1s[t] = w1p;
        if (t < 2) b1s[t] = b1[2 * j + t];
    }

    // readout ownership: warp w -> batches [16w,16w+16); quads own rows b0w+q, +8
    const int b0w = 16 * wid;
    const int rb0 = b0w + (lane >> 2);
    const int rb1 = rb0 + 8;
    const int c0l = 2 * (lane & 3);

    float b2v[8];
    #pragma unroll
    for (int nt = 0; nt < 4; nt++) {
        b2v[nt * 2]     = b2[32 * j + nt * 8 + c0l];
        b2v[nt * 2 + 1] = b2[32 * j + nt * 8 + c0l + 1];
    }

    float zc00 = h0[(size_t)rb0 * HH + 2 * j];
    float zc01 = h0[(size_t)rb0 * HH + 2 * j + 1];
    float zc10 = h0[(size_t)rb1 * HH + 2 * j];
    float zc11 = h0[(size_t)rb1 * HH + 2 * j + 1];
    if ((lane & 3) == 0) {
        g_zT[(2 * j) * BB + rb0]     = zc00;
        g_zT[(2 * j + 1) * BB + rb0] = zc01;
        g_zT[(2 * j) * BB + rb1]     = zc10;
        g_zT[(2 * j + 1) * BB + rb1] = zc11;
        g_zseq[(size_t)(2 * j) * BB + rb0]     = zc00;
        g_zseq[(size_t)(2 * j + 1) * BB + rb0] = zc01;
        g_zseq[(size_t)(2 * j) * BB + rb1]     = zc10;
        g_zseq[(size_t)(2 * j + 1) * BB + rb1] = zc11;
    }

    unsigned ep = 0;
    gridbar(++ep, j, wid, lane);   // weights + z v0 visible everywhere

    #pragma unroll 1
    for (int s = 0; s < NSTEPS; ++s) {
        // ===== stage 1: hid[:, 2j+half] = relu(z @ W1pair + b1) ==================
        {
            unsigned long long acc01;
            if (half == 0) { PACK2(acc01, b1s[0], b1s[1]); }
            else           { PACK2(acc01, 0.f, 0.f); }

            load_chunk64(sbase + SM_XBUF, g_zT, t);
            load_chunk64(sbase + SM_XBUF + 65536u, g_zT + 16384, t);
            CP_WAIT(1);
            __syncthreads();
            #pragma unroll 1
            for (int c = 0; c < 4; ++c) {
                const float* buf = (const float*)(smc + SM_XBUF + (c & 1) * 65536);
                if ((c & 1) == half) {
                    #pragma unroll 8
                    for (int kk = 0; kk < 64; kk++) {
                        float zv = buf[kk * BB + b];
                        unsigned long long aa; PACK2(aa, zv, zv);
                        FMA2(acc01, aa, w1s[c * 64 + kk]);
                    }
                }
                __syncthreads();           // all threads done reading buf (c&1)
                if (c + 2 < 4) {
                    load_chunk64(sbase + SM_XBUF + (unsigned)((c & 1) * 65536),
                                 g_zT + (c + 2) * 16384, t);
                    CP_WAIT(1);
                    __syncthreads();
                } else if (c + 1 < 4) {
                    CP_WAIT(0);
                    __syncthreads();
                }
            }
            psum[t] = acc01;
            __syncthreads();
            unsigned long long other = psum[t ^ 256];
            float slo, shi, olo, ohi;
            UNPACK2(slo, shi, acc01);
            UNPACK2(olo, ohi, other);
            float a0 = fmaxf(slo + olo, 0.f);
            float a1 = fmaxf(shi + ohi, 0.f);
            float a = (half == 0) ? a0 : a1;
            __half hv = __float2half_rn(a);
            float rem = a - __half2float(hv);
            g_hidhi[(size_t)b * HH + 2 * j + half] = hv;
            g_hidlo[(size_t)b * HH + 2 * j + half] = __float2half_rn(rem * LOSCALE);
        }
        gridbar(++ep, j, wid, lane);

        // ---- prefetch this step's d vectors (independent of hid; hides L2 lat)
        float2 dA0, dB0, dA1, dB1;
        {
            const float* dp0 = g_dstep + ((size_t)s * BB + rb0) * CC;
            const float* dp1 = g_dstep + ((size_t)s * BB + rb1) * CC;
            dA0 = *(const float2*)(dp0 + c0l);
            dB0 = *(const float2*)(dp0 + c0l + 8);
            dA1 = *(const float2*)(dp1 + c0l);
            dB1 = *(const float2*)(dp1 + c0l + 8);
        }

        // ===== stage 2: G[256b, 32n] = hid @ W2slice via mma.sync fp16-split ====
        float cfrH[4][4], cfrL[4][4];
        #pragma unroll
        for (int nt = 0; nt < 4; nt++)
            #pragma unroll
            for (int q = 0; q < 4; q++) { cfrH[nt][q] = 0.f; cfrL[nt][q] = 0.f; }

        {
            loadA2(sbase + SM_XBUF, 0, t);
            CP_WAIT(0);
            __syncthreads();
            #pragma unroll 1
            for (int kc = 0; kc < 4; ++kc) {
                if (kc < 3)
                    loadA2(sbase + SM_XBUF + (unsigned)(((kc + 1) & 1) * 65536), kc + 1, t);
                unsigned ab = sbase + SM_XBUF + (unsigned)((kc & 1) * 65536);
                #pragma unroll
                for (int kt = 0; kt < 4; ++kt) {
                    uint32_t ahi[4], alo[4], bh[8], bl[8];
                    ldmA(ahi, ab, b0w, kt, lane);
                    ldmA(alo, ab + 32768u, b0w, kt, lane);
                    int ktg = kc * 4 + kt;
                    ldmB(bh,     sbase + SM_W2HI, 0,  ktg, lane);
                    ldmB(bh + 4, sbase + SM_W2HI, 16, ktg, lane);
                    ldmB(bl,     sbase + SM_W2LO, 0,  ktg, lane);
                    ldmB(bl + 4, sbase + SM_W2LO, 16, ktg, lane);
                    #pragma unroll
                    for (int nt = 0; nt < 4; nt++) {
                        mmaf16(cfrH[nt], ahi, bh + 2 * nt);
                        mmaf16(cfrL[nt], ahi, bl + 2 * nt);
                        mmaf16(cfrL[nt], alo, bh + 2 * nt);
                    }
                }
                if (kc < 3) { CP_WAIT(0); __syncthreads(); }
            }
        }

        // ===== readout: tanh + d contraction, quad reduction =====
        {
            float g[4][4];
            #pragma unroll
            for (int nt = 0; nt < 4; nt++)
                #pragma unroll
                for (int q = 0; q < 4; q++)
                    g[nt][q] = fmaf(cfrL[nt][q], INVLOSCALE, cfrH[nt][q]);

            float s00 = tanhf(g[0][0] + b2v[0]) * dA0.x + tanhf(g[0][1] + b2v[1]) * dA0.y
                      + tanhf(g[1][0] + b2v[2]) * dB0.x + tanhf(g[1][1] + b2v[3]) * dB0.y;
            float s01 = tanhf(g[2][0] + b2v[4]) * dA0.x + tanhf(g[2][1] + b2v[5]) * dA0.y
                      + tanhf(g[3][0] + b2v[6]) * dB0.x + tanhf(g[3][1] + b2v[7]) * dB0.y;
            float s10 = tanhf(g[0][2] + b2v[0]) * dA1.x + tanhf(g[0][3] + b2v[1]) * dA1.y
                      + tanhf(g[1][2] + b2v[2]) * dB1.x + tanhf(g[1][3] + b2v[3]) * dB1.y;
            float s11 = tanhf(g[2][2] + b2v[4]) * dA1.x + tanhf(g[2][3] + b2v[5]) * dA1.y
                      + tanhf(g[3][2] + b2v[6]) * dB1.x + tanhf(g[3][3] + b2v[7]) * dB1.y;

            s00 += __shfl_xor_sync(0xFFFFFFFF, s00, 1); s00 += __shfl_xor_sync(0xFFFFFFFF, s00, 2);
            s01 += __shfl_xor_sync(0xFFFFFFFF, s01, 1); s01 += __shfl_xor_sync(0xFFFFFFFF, s01, 2);
            s10 += __shfl_xor_sync(0xFFFFFFFF, s10, 1); s10 += __shfl_xor_sync(0xFFFFFFFF, s10, 2);
            s11 += __shfl_xor_sync(0xFFFFFFFF, s11, 1); s11 += __shfl_xor_sync(0xFFFFFFFF, s11, 2);

            zc00 += s00; zc01 += s01; zc10 += s10; zc11 += s11;
            if ((lane & 3) == 0) {
                g_zT[(2 * j) * BB + rb0]     = zc00;
                g_zT[(2 * j + 1) * BB + rb0] = zc01;
                g_zT[(2 * j) * BB + rb1]     = zc10;
                g_zT[(2 * j + 1) * BB + rb1] = zc11;
                size_t zs = (size_t)(s + 1) * (HH * BB);
                g_zseq[zs + (2 * j) * BB + rb0]     = zc00;
                g_zseq[zs + (2 * j + 1) * BB + rb0] = zc01;
                g_zseq[zs + (2 * j) * BB + rb1]     = zc10;
                g_zseq[zs + (2 * j + 1) * BB + rb1] = zc11;
            }
        }
        gridbar(++ep, j, wid, lane);
    }
}

// ---------------- final projection ----------------
#define JCH 32
__global__ void __launch_bounds__(256, 2)
final_kernel(const float* __restrict__ dW1, const float* __restrict__ db1,
             const float* __restrict__ dW2, const float* __restrict__ db2,
             float* __restrict__ out) {
    const int l = blockIdx.x, t = threadIdx.x;
    __shared__ float w1s[256 * JCH];
    __shared__ float w2s[JCH * 32];
    __shared__ float db1s[JCH];

    unsigned long long oacc[16];
    #pragma unroll
    for (int q = 0; q < 16; q++) PACK2(oacc[q], db2[2 * q], db2[2 * q + 1]);

    for (int ch = 0; ch < 512 / JCH; ++ch) {
        const int j0 = ch * JCH;
        {
            const float4* src = (const float4*)(dW1 + (size_t)t * 512 + j0);
            float4* dst = (float4*)(w1s + t * JCH);
            #pragma unroll
            for (int q = 0; q < JCH / 4; q++) dst[q] = src[q];
            for (int q = t; q < JCH * 32; q += 256) w2s[q] = dW2[(size_t)j0 * 32 + q];
            if (t < JCH) db1s[t] = db1[j0 + t];
        }
        __syncthreads();

        unsigned long long hacc[JCH / 2];
        #pragma unroll
        for (int p = 0; p < JCH / 2; p++) PACK2(hacc[p], db1s[2 * p], db1s[2 * p + 1]);
        {
            const float* zp = g_zseq + (size_t)l * (HH * BB) + t;
            #pragma unroll 4
            for (int k = 0; k < HH; k++) {
                float zv = zp[(size_t)k * BB];
                unsigned long long aa; PACK2(aa, zv, zv);
                const ulonglong2* wp = (const ulonglong2*)(w1s + k * JCH);
                #pragma unroll
                for (int q = 0; q < JCH / 4; q++) {
                    ulonglong2 w = wp[q];
                    FMA2(hacc[2 * q],     aa, w.x);
                    FMA2(hacc[2 * q + 1], aa, w.y);
                }
            }
        }
        #pragma unroll
        for (int p = 0; p < JCH / 2; p++) {
            float lo, hi; UNPACK2(lo, hi, hacc[p]);
            float t0 = tanh_fast(lo), t1 = tanh_fast(hi);
            unsigned long long aa0, aa1; PACK2(aa0, t0, t0); PACK2(aa1, t1, t1);
            const unsigned long long* r0 = (const unsigned long long*)(w2s + (2 * p) * 32);
            const unsigned long long* r1 = (const unsigned long long*)(w2s + (2 * p + 1) * 32);
            #pragma unroll
            for (int q = 0; q < 16; q++) FMA2(oacc[q], aa0, r0[q]);
            #pragma unroll
            for (int q = 0; q < 16; q++) FMA2(oacc[q], aa1, r1[q]);
        }
        __syncthreads();
    }

    float* op = out + ((size_t)l * BB + t) * YY;
    #pragma unroll
    for (int q = 0; q < 16; q++) {
        float lo, hi; UNPACK2(lo, hi, oacc[q]);
        op[2 * q] = lo; op[2 * q + 1] = hi;
    }
}

// ---------------- launch ----------------
extern "C" void kernel_launch(void* const* d_in, const int* in_sizes, int n_in,
                              void* d_out, int out_size) {
    const float* ts  = (const float*)d_in[0];
    const float* us  = (const float*)d_in[1];
    const float* h0  = (const float*)d_in[2];
    const float* W1  = (const float*)d_in[3];
    const float* b1  = (const float*)d_in[4];
    const float* W2  = (const float*)d_in[5];
    const float* b2  = (const float*)d_in[6];
    const float* dW1 = (const float*)d_in[7];
    const float* db1 = (const float*)d_in[8];
    const float* dW2 = (const float*)d_in[9];
    const float* db2 = (const float*)d_in[10];

    cudaFuncSetAttribute(scan_kernel,
                         cudaFuncAttributeMaxDynamicSharedMemorySize, SMEM_BYTES);

    prep_kernel<<<NSTEPS, 256>>>(ts, us);
    scan_kernel<<<NCTA, NTHR, SMEM_BYTES>>>(W1, b1, W2, b2, h0);
    final_kernel<<<LL, 256>>>(dW1, db1, dW2, db2, (float*)d_out);
}

// round 16
// speedup vs baseline: 1.3816x; 1.0215x over previous
#include <cuda_runtime.h>
#include <cuda_fp16.h>
#include <cstdint>
#include <math.h>

#define LL 256
#define BB 256
#define HH 256
#define CC 16
#define YY 32
#define NSTEPS 255
#define NCTA 128
#define NTHR 512
#define LOSCALE 2048.0f
#define INVLOSCALE 4.8828125e-4f

// ---- dynamic smem byte offsets (verified: 40960 + 131072 = 172032) ----
#define SM_W2HI 0          // 16 KB  W2t hi fp16, blocked SW128
#define SM_W2LO 16384      // 16 KB  W2t lo (x2048)
#define SM_W1   32768      // 2 KB   ull[256]
#define SM_B1   34816      // 8 B
#define SM_PSUM 35072      // 4 KB
#define SM_XBUF 40960      // 128 KB: stage1 2x64KB fp32 / stage2 2x64KB fp16 A bufs
#define SMEM_BYTES 172032

// ---------------- global scratch ----------------
__device__ float g_zT[HH * BB];                 // z transposed [h][b] fp32
__device__ __half g_hidhi[BB * HH];             // hid [b][h] fp16 hi
__device__ __half g_hidlo[BB * HH];             // hid [b][h] fp16 lo (x2048)
__device__ float g_dstep[NSTEPS * BB * CC];
__device__ float g_zseq[LL * HH * BB];
__device__ unsigned g_bar_count;

// ---------------- fast tanh (final kernel only; no recurrence amplification) -
__device__ __forceinline__ float tanh_fast(float x) {
    float e = __expf(2.0f * x);
    return 1.0f - __fdividef(2.0f, e + 1.0f);
}

// ---------------- packed f32x2 helpers ----------------
#define FMA2(acc, a, b) asm("fma.rn.f32x2 %0, %1, %2, %0;" : "+l"(acc) : "l"(a), "l"(b))
#define PACK2(r, lo, hi) asm("mov.b64 %0, {%1, %2};" : "=l"(r) : "f"(lo), "f"(hi))
#define UNPACK2(lo, hi, r) asm("mov.b64 {%0, %1}, %2;" : "=f"(lo), "=f"(hi) : "l"(r))

// ---------------- cp.async ----------------
__device__ __forceinline__ void cpasync16(unsigned saddr, const void* g) {
    asm volatile("cp.async.cg.shared.global [%0], [%1], 16;" :: "r"(saddr), "l"(g));
}
#define CP_COMMIT() asm volatile("cp.async.commit_group;")
#define CP_WAIT(n)  asm volatile("cp.async.wait_group %0;" :: "n"(n))

// stage1: one 64x256 fp32 chunk (64 KB), 512 threads x 8 x 16B
__device__ __forceinline__ void load_chunk64(unsigned sdst, const float* src, int t) {
    unsigned s = sdst + (unsigned)t * 16u;
    const float* g = src + t * 4;
    #pragma unroll
    for (int i = 0; i < 8; i++)
        cpasync16(s + i * 8192u, g + i * 2048);
    CP_COMMIT();
}

// stage2: one 256b x 64k fp16 A chunk (hi 32KB + lo 32KB), SW128-swizzled rows
__device__ __forceinline__ void loadA2(unsigned base, int kc, int t) {
    #pragma unroll
    for (int i = 0; i < 4; i++) {
        int u = t * 4 + i;                  // 0..2047
        int row = u >> 3, seg = u & 7;
        unsigned sw = (unsigned)(row * 128 + ((seg ^ (row & 7)) << 4));
        cpasync16(base + sw, g_hidhi + (size_t)row * HH + kc * 64 + seg * 8);
    }
    #pragma unroll
    for (int i = 0; i < 4; i++) {
        int u = t * 4 + i;
        int row = u >> 3, seg = u & 7;
        unsigned sw = (unsigned)(row * 128 + ((seg ^ (row & 7)) << 4));
        cpasync16(base + 32768u + sw, g_hidlo + (size_t)row * HH + kc * 64 + seg * 8);
    }
    CP_COMMIT();
}

// ---------------- ldmatrix / mma ----------------
__device__ __forceinline__ void ldmA(uint32_t* r, unsigned abase, int b0, int kt, int lane) {
    int q = lane >> 3;
    int row = b0 + (lane & 7) + ((q & 1) << 3);
    int seg = 2 * kt + (q >> 1);
    unsigned addr = abase + (unsigned)(row * 128 + ((seg ^ (row & 7)) << 4));
    asm volatile("ldmatrix.sync.aligned.m8n8.x4.shared.b16 {%0,%1,%2,%3}, [%4];"
        : "=r"(r[0]), "=r"(r[1]), "=r"(r[2]), "=r"(r[3]) : "r"(addr));
}

// W2t blocked: byte(n,k) = ((n>>3)+(k>>6)*4)*1024 + (n&7)*128 + (k&63)*2, XOR-swizzled
__device__ __forceinline__ void ldmB(uint32_t* r, unsigned mbase, int n0, int ktg, int lane) {
    int sel = lane >> 3;
    int n = n0 + ((sel >> 1) << 3) + (lane & 7);
    int k = ktg * 16 + ((sel & 1) << 3);
    unsigned byte = (unsigned)((((n >> 3) + (k >> 6) * 4) << 10) + ((n & 7) << 7) + ((k & 63) << 1));
    unsigned sw = byte ^ ((byte >> 3) & 0x70u);
    asm volatile("ldmatrix.sync.aligned.m8n8.x4.shared.b16 {%0,%1,%2,%3}, [%4];"
        : "=r"(r[0]), "=r"(r[1]), "=r"(r[2]), "=r"(r[3]) : "r"(mbase + sw));
}

__device__ __forceinline__ void mmaf16(float* c, const uint32_t* a, const uint32_t* b) {
    asm volatile("mma.sync.aligned.m16n8k16.row.col.f32.f16.f16.f32 "
        "{%0,%1,%2,%3}, {%4,%5,%6,%7}, {%8,%9}, {%0,%1,%2,%3};"
        : "+f"(c[0]), "+f"(c[1]), "+f"(c[2]), "+f"(c[3])
        : "r"(a[0]), "r"(a[1]), "r"(a[2]), "r"(a[3]), "r"(b[0]), "r"(b[1]));
}

// ---------------- grid barrier (single counter; hot-spin wakeup) --------------
// Release fence only (consumers read via cp.async.cg -> L2 coherence point).
// Hot spin: no __nanosleep -- its coarse wakeup quantization sits on the
// critical path of all 510 barriers; pure volatile-load polling detects the
// release within one L2 round trip.
__device__ __forceinline__ void gridbar(unsigned target) {
    __threadfence();                 // release: drain my stores to L2
    __syncthreads();
    if (threadIdx.x == 0) {
        atomicAdd(&g_bar_count, 1u);
        volatile unsigned* p = &g_bar_count;
        while (*p < target) { }
    }
    __syncthreads();
}

// ---------------- prep ----------------
__device__ __forceinline__ float Xv(const float* ts, const float* us, int l, int b, int c) {
    return (c == 0) ? ts[(size_t)l * BB + b]
                    : us[((size_t)l * BB + b) * (CC - 1) + (c - 1)];
}

__global__ void prep_kernel(const float* __restrict__ ts, const float* __restrict__ us) {
    int k = blockIdx.x;
    int b = threadIdx.x;
    if (k == 0 && b == 0) g_bar_count = 0u;

    float s  = ts[(size_t)k * BB];
    float dt = ts[(size_t)(k + 1) * BB] - s;
    int idx = (int)floorf(s);
    idx = idx < 0 ? 0 : (idx > LL - 2 ? LL - 2 : idx);
    float tau = s - (float)idx;
    float h00p = 6.f * tau * tau - 6.f * tau;
    float h10p = 3.f * tau * tau - 4.f * tau + 1.f;
    float h11p = 3.f * tau * tau - 2.f * tau;

    float* dst = g_dstep + ((size_t)k * BB + b) * CC;
    #pragma unroll
    for (int c = 0; c < CC; c++) {
        float x_i  = Xv(ts, us, idx, b, c);
        float x_ip = Xv(ts, us, idx + 1, b, c);
        float di   = (idx == 0) ? (x_ip - x_i) : (x_i - Xv(ts, us, idx - 1, b, c));
        float dip  = x_ip - x_i;
        float val  = h00p * (x_i - x_ip) + h10p * di + h11p * dip;
        dst[c] = dt * val;
    }
}

// ---------------- persistent scan kernel (R12 structure) ----------------------
__global__ void __launch_bounds__(NTHR, 1)
scan_kernel(const float* __restrict__ W1, const float* __restrict__ b1,
            const float* __restrict__ W2, const float* __restrict__ b2,
            const float* __restrict__ h0) {
    extern __shared__ char smc[];
    const unsigned sbase = (unsigned)__cvta_generic_to_shared(smc);
    float* b1s = (float*)(smc + SM_B1);
    unsigned long long* w1s  = (unsigned long long*)(smc + SM_W1);
    unsigned long long* psum = (unsigned long long*)(smc + SM_PSUM);

    const int t    = threadIdx.x;
    const int b    = t & 255;
    const int half = t >> 8;
    const int wid  = t >> 5;
    const int lane = t & 31;
    const int j    = blockIdx.x;

    // --- one-time: W2 slice -> fp16 hi/lo(x2048), transposed [n][k], blocked SW128
    for (int idx = t; idx < 32 * 256; idx += NTHR) {
        int n = idx >> 8, k = idx & 255;
        float w = W2[(size_t)k * (HH * CC) + 32 * j + n];
        __half whi = __float2half_rn(w);
        float rem = w - __half2float(whi);
        unsigned byte = (unsigned)((((n >> 3) + (k >> 6) * 4) << 10) + ((n & 7) << 7) + ((k & 63) << 1));
        unsigned sw = byte ^ ((byte >> 3) & 0x70u);
        *(__half*)(smc + SM_W2HI + sw) = whi;
        *(__half*)(smc + SM_W2LO + sw) = __float2half_rn(rem * LOSCALE);
    }
    if (t < 256) {
        float2 w1v = *(const float2*)(W1 + (size_t)t * HH + 2 * j);
        unsigned long long w1p; PACK2(w1p, w1v.x, w1v.y);
        w1s[t] = w1p;
        if (t < 2) b1s[t] = b1[2 * j + t];
    }

    // readout ownership: warp w -> batches [16w,16w+16); quads own rows b0w+q, +8
    const int b0w = 16 * wid;
    const int rb0 = b0w + (lane >> 2);
    const int rb1 = rb0 + 8;
    const int c0l = 2 * (lane & 3);

    float b2v[8];
    #pragma unroll
    for (int nt = 0; nt < 4; nt++) {
        b2v[nt * 2]     = b2[32 * j + nt * 8 + c0l];
        b2v[nt * 2 + 1] = b2[32 * j + nt * 8 + c0l + 1];
    }

    float zc00 = h0[(size_t)rb0 * HH + 2 * j];
    float zc01 = h0[(size_t)rb0 * HH + 2 * j + 1];
    float zc10 = h0[(size_t)rb1 * HH + 2 * j];
    float zc11 = h0[(size_t)rb1 * HH + 2 * j + 1];
    if ((lane & 3) == 0) {
        g_zT[(2 * j) * BB + rb0]     = zc00;
        g_zT[(2 * j + 1) * BB + rb0] = zc01;
        g_zT[(2 * j) * BB + rb1]     = zc10;
        g_zT[(2 * j + 1) * BB + rb1] = zc11;
        g_zseq[(size_t)(2 * j) * BB + rb0]     = zc00;
        g_zseq[(size_t)(2 * j + 1) * BB + rb0] = zc01;
        g_zseq[(size_t)(2 * j) * BB + rb1]     = zc10;
        g_zseq[(size_t)(2 * j + 1) * BB + rb1] = zc11;
    }

    unsigned ep = 0;
    gridbar((++ep) * NCTA);   // weights + z v0 visible everywhere

    #pragma unroll 1
    for (int s = 0; s < NSTEPS; ++s) {
        // ===== stage 1: hid[:, 2j+half] = relu(z @ W1pair + b1) ==================
        {
            unsigned long long acc01;
            if (half == 0) { PACK2(acc01, b1s[0], b1s[1]); }
            else           { PACK2(acc01, 0.f, 0.f); }

            load_chunk64(sbase + SM_XBUF, g_zT, t);
            load_chunk64(sbase + SM_XBUF + 65536u, g_zT + 16384, t);
            CP_WAIT(1);
            __syncthreads();
            #pragma unroll 1
            for (int c = 0; c < 4; ++c) {
                const float* buf = (const float*)(smc + SM_XBUF + (c & 1) * 65536);
                if ((c & 1) == half) {
                    #pragma unroll 8
                    for (int kk = 0; kk < 64; kk++) {
                        float zv = buf[kk * BB + b];
                        unsigned long long aa; PACK2(aa, zv, zv);
                        FMA2(acc01, aa, w1s[c * 64 + kk]);
                    }
                }
                __syncthreads();           // all threads done reading buf (c&1)
                if (c + 2 < 4) {
                    load_chunk64(sbase + SM_XBUF + (unsigned)((c & 1) * 65536),
                                 g_zT + (c + 2) * 16384, t);
                    CP_WAIT(1);
                    __syncthreads();
                } else if (c + 1 < 4) {
                    CP_WAIT(0);
                    __syncthreads();
                }
            }
            psum[t] = acc01;
            __syncthreads();
            unsigned long long other = psum[t ^ 256];
            float slo, shi, olo, ohi;
            UNPACK2(slo, shi, acc01);
            UNPACK2(olo, ohi, other);
            float a0 = fmaxf(slo + olo, 0.f);
            float a1 = fmaxf(shi + ohi, 0.f);
            float a = (half == 0) ? a0 : a1;
            __half hv = __float2half_rn(a);
            float rem = a - __half2float(hv);
            g_hidhi[(size_t)b * HH + 2 * j + half] = hv;
            g_hidlo[(size_t)b * HH + 2 * j + half] = __float2half_rn(rem * LOSCALE);
        }
        gridbar((++ep) * NCTA);

        // ---- prefetch this step's d vectors (independent of hid; hides L2 lat)
        float2 dA0, dB0, dA1, dB1;
        {
            const float* dp0 = g_dstep + ((size_t)s * BB + rb0) * CC;
            const float* dp1 = g_dstep + ((size_t)s * BB + rb1) * CC;
            dA0 = *(const float2*)(dp0 + c0l);
            dB0 = *(const float2*)(dp0 + c0l + 8);
            dA1 = *(const float2*)(dp1 + c0l);
            dB1 = *(const float2*)(dp1 + c0l + 8);
        }

        // ===== stage 2: G[256b, 32n] = hid @ W2slice via mma.sync fp16-split ====
        float cfrH[4][4], cfrL[4][4];
        #pragma unroll
        for (int nt = 0; nt < 4; nt++)
            #pragma unroll
            for (int q = 0; q < 4; q++) { cfrH[nt][q] = 0.f; cfrL[nt][q] = 0.f; }

        {
            loadA2(sbase + SM_XBUF, 0, t);
            CP_WAIT(0);
            __syncthreads();
            #pragma unroll 1
            for (int kc = 0; kc < 4; ++kc) {
                if (kc < 3)
                    loadA2(sbase + SM_XBUF + (unsigned)(((kc + 1) & 1) * 65536), kc + 1, t);
                unsigned ab = sbase + SM_XBUF + (unsigned)((kc & 1) * 65536);
                #pragma unroll
                for (int kt = 0; kt < 4; ++kt) {
                    uint32_t ahi[4], alo[4], bh[8], bl[8];
                    ldmA(ahi, ab, b0w, kt, lane);
                    ldmA(alo, ab + 32768u, b0w, kt, lane);
                    int ktg = kc * 4 + kt;
                    ldmB(bh,     sbase + SM_W2HI, 0,  ktg, lane);
                    ldmB(bh + 4, sbase + SM_W2HI, 16, ktg, lane);
                    ldmB(bl,     sbase + SM_W2LO, 0,  ktg, lane);
                    ldmB(bl + 4, sbase + SM_W2LO, 16, ktg, lane);
                    #pragma unroll
                    for (int nt = 0; nt < 4; nt++) {
                        mmaf16(cfrH[nt], ahi, bh + 2 * nt);
                        mmaf16(cfrL[nt], ahi, bl + 2 * nt);
                        mmaf16(cfrL[nt], alo, bh + 2 * nt);
                    }
                }
                if (kc < 3) { CP_WAIT(0); __syncthreads(); }
            }
        }

        // ===== readout: tanh + d contraction, quad reduction =====
        {
            float g[4][4];
            #pragma unroll
            for (int nt = 0; nt < 4; nt++)
                #pragma unroll
                for (int q = 0; q < 4; q++)
                    g[nt][q] = fmaf(cfrL[nt][q], INVLOSCALE, cfrH[nt][q]);

            float s00 = tanhf(g[0][0] + b2v[0]) * dA0.x + tanhf(g[0][1] + b2v[1]) * dA0.y
                      + tanhf(g[1][0] + b2v[2]) * dB0.x + tanhf(g[1][1] + b2v[3]) * dB0.y;
            float s01 = tanhf(g[2][0] + b2v[4]) * dA0.x + tanhf(g[2][1] + b2v[5]) * dA0.y
                      + tanhf(g[3][0] + b2v[6]) * dB0.x + tanhf(g[3][1] + b2v[7]) * dB0.y;
            float s10 = tanhf(g[0][2] + b2v[0]) * dA1.x + tanhf(g[0][3] + b2v[1]) * dA1.y
                      + tanhf(g[1][2] + b2v[2]) * dB1.x + tanhf(g[1][3] + b2v[3]) * dB1.y;
            float s11 = tanhf(g[2][2] + b2v[4]) * dA1.x + tanhf(g[2][3] + b2v[5]) * dA1.y
                      + tanhf(g[3][2] + b2v[6]) * dB1.x + tanhf(g[3][3] + b2v[7]) * dB1.y;

            s00 += __shfl_xor_sync(0xFFFFFFFF, s00, 1); s00 += __shfl_xor_sync(0xFFFFFFFF, s00, 2);
            s01 += __shfl_xor_sync(0xFFFFFFFF, s01, 1); s01 += __shfl_xor_sync(0xFFFFFFFF, s01, 2);
            s10 += __shfl_xor_sync(0xFFFFFFFF, s10, 1); s10 += __shfl_xor_sync(0xFFFFFFFF, s10, 2);
            s11 += __shfl_xor_sync(0xFFFFFFFF, s11, 1); s11 += __shfl_xor_sync(0xFFFFFFFF, s11, 2);

            zc00 += s00; zc01 += s01; zc10 += s10; zc11 += s11;
            if ((lane & 3) == 0) {
                g_zT[(2 * j) * BB + rb0]     = zc00;
                g_zT[(2 * j + 1) * BB + rb0] = zc01;
                g_zT[(2 * j) * BB + rb1]     = zc10;
                g_zT[(2 * j + 1) * BB + rb1] = zc11;
                size_t zs = (size_t)(s + 1) * (HH * BB);
                g_zseq[zs + (2 * j) * BB + rb0]     = zc00;
                g_zseq[zs + (2 * j + 1) * BB + rb0] = zc01;
                g_zseq[zs + (2 * j) * BB + rb1]     = zc10;
                g_zseq[zs + (2 * j + 1) * BB + rb1] = zc11;
            }
        }
        gridbar((++ep) * NCTA);
    }
}

// ---------------- final projection ----------------
#define JCH 32
__global__ void __launch_bounds__(256, 2)
final_kernel(const float* __restrict__ dW1, const float* __restrict__ db1,
             const float* __restrict__ dW2, const float* __restrict__ db2,
             float* __restrict__ out) {
    const int l = blockIdx.x, t = threadIdx.x;
    __shared__ float w1s[256 * JCH];
    __shared__ float w2s[JCH * 32];
    __shared__ float db1s[JCH];

    unsigned long long oacc[16];
    #pragma unroll
    for (int q = 0; q < 16; q++) PACK2(oacc[q], db2[2 * q], db2[2 * q + 1]);

    for (int ch = 0; ch < 512 / JCH; ++ch) {
        const int j0 = ch * JCH;
        {
            const float4* src = (const float4*)(dW1 + (size_t)t * 512 + j0);
            float4* dst = (float4*)(w1s + t * JCH);
            #pragma unroll
            for (int q = 0; q < JCH / 4; q++) dst[q] = src[q];
            for (int q = t; q < JCH * 32; q += 256) w2s[q] = dW2[(size_t)j0 * 32 + q];
            if (t < JCH) db1s[t] = db1[j0 + t];
        }
        __syncthreads();

        unsigned long long hacc[JCH / 2];
        #pragma unroll
        for (int p = 0; p < JCH / 2; p++) PACK2(hacc[p], db1s[2 * p], db1s[2 * p + 1]);
        {
            const float* zp = g_zseq + (size_t)l * (HH * BB) + t;
            #pragma unroll 4
            for (int k = 0; k < HH; k++) {
                float zv = zp[(size_t)k * BB];
                unsigned long long aa; PACK2(aa, zv, zv);
                const ulonglong2* wp = (const ulonglong2*)(w1s + k * JCH);
                #pragma unroll
                for (int q = 0; q < JCH / 4; q++) {
                    ulonglong2 w = wp[q];
                    FMA2(hacc[2 * q],     aa, w.x);
                    FMA2(hacc[2 * q + 1], aa, w.y);
                }
            }
        }
        #pragma unroll
        for (int p = 0; p < JCH / 2; p++) {
            float lo, hi; UNPACK2(lo, hi, hacc[p]);
            float t0 = tanh_fast(lo), t1 = tanh_fast(hi);
            unsigned long long aa0, aa1; PACK2(aa0, t0, t0); PACK2(aa1, t1, t1);
            const unsigned long long* r0 = (const unsigned long long*)(w2s + (2 * p) * 32);
            const unsigned long long* r1 = (const unsigned long long*)(w2s + (2 * p + 1) * 32);
            #pragma unroll
            for (int q = 0; q < 16; q++) FMA2(oacc[q], aa0, r0[q]);
            #pragma unroll
            for (int q = 0; q < 16; q++) FMA2(oacc[q], aa1, r1[q]);
        }
        __syncthreads();
    }

    float* op = out + ((size_t)l * BB + t) * YY;
    #pragma unroll
    for (int q = 0; q < 16; q++) {
        float lo, hi; UNPACK2(lo, hi, oacc[q]);
        op[2 * q] = lo; op[2 * q + 1] = hi;
    }
}

// ---------------- launch ----------------
extern "C" void kernel_launch(void* const* d_in, const int* in_sizes, int n_in,
                              void* d_out, int out_size) {
    const float* ts  = (const float*)d_in[0];
    const float* us  = (const float*)d_in[1];
    const float* h0  = (const float*)d_in[2];
    const float* W1  = (const float*)d_in[3];
    const float* b1  = (const float*)d_in[4];
    const float* W2  = (const float*)d_in[5];
    const float* b2  = (const float*)d_in[6];
    const float* dW1 = (const float*)d_in[7];
    const float* db1 = (const float*)d_in[8];
    const float* dW2 = (const float*)d_in[9];
    const float* db2 = (const float*)d_in[10];

    cudaFuncSetAttribute(scan_kernel,
                         cudaFuncAttributeMaxDynamicSharedMemorySize, SMEM_BYTES);

    prep_kernel<<<NSTEPS, 256>>>(ts, us);
    scan_kernel<<<NCTA, NTHR, SMEM_BYTES>>>(W1, b1, W2, b2, h0);
    final_kernel<<<LL, 256>>>(dW1, db1, dW2, db2, (float*)d_out);
}